// round 16
// baseline (speedup 1.0000x reference)
#include <cuda_runtime.h>
#include <cuda_fp16.h>
#include <cstdint>

#define QDIM 4096   // q_dim (output rows i)
#define NDIM 4096   // contraction of GEMM1 (n)
#define MDIM 8192   // softmax dim / contraction of GEMM2 (j)
#define VDIM 4096   // v_dim (output cols v)
#define GX1  (MDIM / 256)   // GEMM1 grid.x = 32 partials per row

// ---------------- scratch (static device globals) ---------------------------
__device__ __half g_Qt[(size_t)QDIM * NDIM];   // Qt[i][n] = Q[n][i]
__device__ __half g_Kt[(size_t)MDIM * NDIM];   // Kt[j][n] = K[n][j]
__device__ __half g_Vc[(size_t)VDIM * MDIM];   // Vc[v][j] = V[v][j]
__device__ __half g_P [(size_t)QDIM * MDIM];   // exp(s) UNNORMALIZED fp16
__device__ float  g_psum[(size_t)QDIM * GX1];  // per-CTA partial row sums
__device__ float  g_rinv[QDIM];                // 1 / row sums

// ---------------- helpers ----------------------------------------------------
__device__ __forceinline__ uint32_t smem_u32(const void* p) {
    uint32_t a;
    asm("{ .reg .u64 t; cvta.to.shared.u64 t, %1; cvt.u32.u64 %0, t; }" : "=r"(a) : "l"(p));
    return a;
}
__device__ __forceinline__ void cp16(uint32_t dst, const void* src) {
    asm volatile("cp.async.cg.shared.global [%0], [%1], 16;" :: "r"(dst), "l"(src));
}
__device__ __forceinline__ void ldsm4(uint32_t& r0, uint32_t& r1, uint32_t& r2, uint32_t& r3,
                                      uint32_t addr) {
    asm volatile("ldmatrix.sync.aligned.m8n8.x4.shared.b16 {%0,%1,%2,%3}, [%4];"
                 : "=r"(r0), "=r"(r1), "=r"(r2), "=r"(r3) : "r"(addr));
}
__device__ __forceinline__ void mma16816(float* d, uint32_t a0, uint32_t a1, uint32_t a2,
                                         uint32_t a3, uint32_t b0, uint32_t b1) {
    asm volatile(
        "mma.sync.aligned.m16n8k16.row.col.f32.f16.f16.f32 "
        "{%0,%1,%2,%3}, {%4,%5,%6,%7}, {%8,%9}, {%0,%1,%2,%3};"
        : "+f"(d[0]), "+f"(d[1]), "+f"(d[2]), "+f"(d[3])
        : "r"(a0), "r"(a1), "r"(a2), "r"(a3), "r"(b0), "r"(b1));
}

// ---------------- preprocessing ----------------------------------------------
// Vectorized 64x64 transpose: out[c][r] = (half) in[r][c].
__global__ __launch_bounds__(256)
void transpose_f2h_v(const float* __restrict__ in, __half* __restrict__ out,
                     int rows, int cols) {
    __shared__ float tile[64][65];
    const int c0 = blockIdx.x * 64, r0 = blockIdx.y * 64;
    const int tid = threadIdx.x;
    const int lr = tid >> 4, lc = tid & 15;
    #pragma unroll
    for (int i = 0; i < 4; i++) {
        int r = lr + i * 16;
        float4 v = *reinterpret_cast<const float4*>(&in[(size_t)(r0 + r) * cols + c0 + lc * 4]);
        tile[r][lc * 4 + 0] = v.x; tile[r][lc * 4 + 1] = v.y;
        tile[r][lc * 4 + 2] = v.z; tile[r][lc * 4 + 3] = v.w;
    }
    __syncthreads();
    const int oc = tid >> 3, och = tid & 7;
    #pragma unroll
    for (int i = 0; i < 2; i++) {
        int c = oc + i * 32;
        __half h[8];
        #pragma unroll
        for (int j = 0; j < 8; j++) h[j] = __float2half(tile[och * 8 + j][c]);
        *reinterpret_cast<uint4*>(&out[(size_t)(c0 + c) * rows + r0 + och * 8]) =
            *reinterpret_cast<uint4*>(h);
    }
}

__global__ void convert_f2h(const float* __restrict__ in, __half* __restrict__ out, size_t n) {
    size_t i = ((size_t)blockIdx.x * blockDim.x + threadIdx.x) * 4;
    if (i + 3 < n) {
        float4 v = *reinterpret_cast<const float4*>(in + i);
        *reinterpret_cast<__half2*>(out + i)     = __floats2half2_rn(v.x, v.y);
        *reinterpret_cast<__half2*>(out + i + 2) = __floats2half2_rn(v.z, v.w);
    }
}

// =============================================================================
// GEMM1 (R13 measured 702-706us, untouched): 512 thr, 128x256, warp 32x64,
// 4 stages, unrolled by 4. C = exp(scale*acc) fp16 + fused psum.
// =============================================================================
#define BM1 128
#define BN1 256
#define BKC 64
#define STAGES1 4
#define STG1_BYTES ((BM1 + BN1) * 128)        // 48 KB
#define SMEM1_SZ (STAGES1 * STG1_BYTES)       // 192 KB

__global__ __launch_bounds__(512, 1)
void gemm1_mma(const __half* __restrict__ A, const __half* __restrict__ B,
               __half* __restrict__ C, float* __restrict__ psum,
               int M, int N, int K) {
    extern __shared__ char smem[];
    const uint32_t sb = smem_u32(smem);
    const int tid = threadIdx.x;
    const int wid = tid >> 5;
    const int lane = tid & 31;
    const int wm = wid & 3;
    const int wn = wid >> 2;
    const size_t m0 = (size_t)blockIdx.y * BM1;
    const size_t n0 = (size_t)blockIdx.x * BN1;
    const int nk = K / BKC;

    const int ldrow = tid >> 3;
    const int ldc16 = tid & 7;
    const uint32_t swz_st = ((uint32_t)ldc16 ^ ((uint32_t)ldrow & 7)) << 4;

    auto load_stage = [&](int c, int buf) {
        const uint32_t abase = sb + buf * STG1_BYTES;
        const uint32_t bbase = abase + BM1 * 128;
        const size_t k0 = (size_t)c * BKC;
        #pragma unroll
        for (int i = 0; i < 2; i++) {
            int row = ldrow + i * 64;
            cp16(abase + row * 128 + swz_st, A + (m0 + row) * (size_t)K + k0 + ldc16 * 8);
        }
        #pragma unroll
        for (int i = 0; i < 4; i++) {
            int row = ldrow + i * 64;
            cp16(bbase + row * 128 + swz_st, B + (n0 + row) * (size_t)K + k0 + ldc16 * 8);
        }
        asm volatile("cp.async.commit_group;" ::: "memory");
    };

    float acc[2][8][4];
    #pragma unroll
    for (int i = 0; i < 2; i++)
        #pragma unroll
        for (int j = 0; j < 8; j++)
            #pragma unroll
            for (int r = 0; r < 4; r++) acc[i][j][r] = 0.0f;

    #pragma unroll
    for (int s = 0; s < STAGES1 - 1; s++) load_stage(s, s);

    const uint32_t lrow = lane & 15;
    const uint32_t lhalf = lane >> 4;
    const uint32_t lswz = lane & 7;
    const uint32_t a_rowbyte = (wm * 32 + lrow) * 128;
    const uint32_t b_rowbyte = (wn * 64 + lrow) * 128;
    uint32_t coff[4];
    #pragma unroll
    for (int k16 = 0; k16 < 4; k16++)
        coff[k16] = (((uint32_t)k16 * 2 + lhalf) ^ lswz) << 4;

    for (int it0 = 0; it0 < nk; it0 += STAGES1) {
        #pragma unroll
        for (int u = 0; u < STAGES1; u++) {
            const int it = it0 + u;
            const int rem = nk - 1 - it;
            if (rem >= 2)      asm volatile("cp.async.wait_group 2;" ::: "memory");
            else if (rem == 1) asm volatile("cp.async.wait_group 1;" ::: "memory");
            else               asm volatile("cp.async.wait_group 0;" ::: "memory");
            __syncthreads();
            if (it + STAGES1 - 1 < nk)
                load_stage(it + STAGES1 - 1, (u + STAGES1 - 1) % STAGES1);

            const uint32_t abase = sb + u * STG1_BYTES;
            const uint32_t bbase = abase + BM1 * 128;

            #pragma unroll
            for (int k16 = 0; k16 < 4; k16++) {
                uint32_t a[2][4], b[4][4];
                #pragma unroll
                for (int mi = 0; mi < 2; mi++)
                    ldsm4(a[mi][0], a[mi][1], a[mi][2], a[mi][3],
                          abase + a_rowbyte + mi * 2048 + coff[k16]);
                #pragma unroll
                for (int ni = 0; ni < 4; ni++)
                    ldsm4(b[ni][0], b[ni][1], b[ni][2], b[ni][3],
                          bbase + b_rowbyte + ni * 2048 + coff[k16]);
                #pragma unroll
                for (int mi = 0; mi < 2; mi++)
                    #pragma unroll
                    for (int nj = 0; nj < 8; nj++)
                        mma16816(acc[mi][nj], a[mi][0], a[mi][1], a[mi][2], a[mi][3],
                                 b[nj >> 1][nj & 1], b[nj >> 1][(nj & 1) + 2]);
            }
        }
    }

    const float scale = 0.015625f;     // 1/sqrt(4096)
    float s0[2], s1[2];
    #pragma unroll
    for (int mi = 0; mi < 2; mi++) { s0[mi] = 0.0f; s1[mi] = 0.0f; }
    #pragma unroll
    for (int mi = 0; mi < 2; mi++) {
        const size_t r0 = m0 + wm * 32 + mi * 16 + (lane >> 2);
        const size_t r1 = r0 + 8;
        #pragma unroll
        for (int nj = 0; nj < 8; nj++) {
            const size_t col = n0 + wn * 64 + nj * 8 + (lane & 3) * 2;
            float* c = acc[mi][nj];
            float e0 = __expf(c[0] * scale), e1 = __expf(c[1] * scale);
            float e2 = __expf(c[2] * scale), e3 = __expf(c[3] * scale);
            *reinterpret_cast<__half2*>(&C[r0 * (size_t)N + col]) = __floats2half2_rn(e0, e1);
            *reinterpret_cast<__half2*>(&C[r1 * (size_t)N + col]) = __floats2half2_rn(e2, e3);
            s0[mi] += e0 + e1;
            s1[mi] += e2 + e3;
        }
    }
    float* red = reinterpret_cast<float*>(smem);
    __syncthreads();
    #pragma unroll
    for (int mi = 0; mi < 2; mi++) {
        float a = s0[mi], b = s1[mi];
        a += __shfl_xor_sync(0xFFFFFFFFu, a, 1);
        a += __shfl_xor_sync(0xFFFFFFFFu, a, 2);
        b += __shfl_xor_sync(0xFFFFFFFFu, b, 1);
        b += __shfl_xor_sync(0xFFFFFFFFu, b, 2);
        if ((lane & 3) == 0) {
            int rl = wm * 32 + mi * 16 + (lane >> 2);
            red[rl * 4 + wn] = a;
            red[(rl + 8) * 4 + wn] = b;
        }
    }
    __syncthreads();
    if (tid < BM1) {
        float s = red[tid * 4] + red[tid * 4 + 1] + red[tid * 4 + 2] + red[tid * 4 + 3];
        psum[(m0 + tid) * GX1 + blockIdx.x] = s;
    }
}

// ---------------- reduce psum partials -> rinv -------------------------------
__global__ __launch_bounds__(256)
void rowsum_recip2(const float* __restrict__ psum, float* __restrict__ rinv) {
    const int row = blockIdx.x * 8 + (threadIdx.x >> 5);
    const int lane = threadIdx.x & 31;
    float v = psum[(size_t)row * GX1 + lane];
    #pragma unroll
    for (int o = 16; o > 0; o >>= 1) v += __shfl_xor_sync(0xFFFFFFFFu, v, o);
    if (lane == 0) rinv[row] = 1.0f / v;
}

// =============================================================================
// GEMM2: 512 thr, 128x128, warp 32x32, 3 stages, 2 CTAs/SM,
// k16-level fragment double-buffering (16 warps/SM + register headroom).
// C = acc * rinv[row] fp32
// =============================================================================
#define BM2 128
#define BN2 128
#define STAGES2 3
#define STG2_BYTES ((BM2 + BN2) * 128)        // 32 KB
#define SMEM2_SZ (STAGES2 * STG2_BYTES)       // 96 KB

__global__ __launch_bounds__(512, 2)
void gemm2_mma(const __half* __restrict__ A, const __half* __restrict__ B,
               float* __restrict__ C, int M, int N, int K,
               const float* __restrict__ rinv) {
    extern __shared__ char smem[];
    const uint32_t sb = smem_u32(smem);
    const int tid = threadIdx.x;
    const int wid = tid >> 5;
    const int lane = tid & 31;
    const int wm = wid & 3;
    const int wn = wid >> 2;
    const size_t m0 = (size_t)blockIdx.y * BM2;
    const size_t n0 = (size_t)blockIdx.x * BN2;
    const int nk = K / BKC;

    const int ldrow = tid >> 3;
    const int ldc16 = tid & 7;
    const uint32_t swz_st = ((uint32_t)ldc16 ^ ((uint32_t)ldrow & 7)) << 4;

    auto load_stage = [&](int c, int buf) {
        const uint32_t abase = sb + buf * STG2_BYTES;
        const uint32_t bbase = abase + BM2 * 128;
        const size_t k0 = (size_t)c * BKC;
        #pragma unroll
        for (int i = 0; i < 2; i++) {
            int row = ldrow + i * 64;
            cp16(abase + row * 128 + swz_st, A + (m0 + row) * (size_t)K + k0 + ldc16 * 8);
        }
        #pragma unroll
        for (int i = 0; i < 2; i++) {
            int row = ldrow + i * 64;
            cp16(bbase + row * 128 + swz_st, B + (n0 + row) * (size_t)K + k0 + ldc16 * 8);
        }
        asm volatile("cp.async.commit_group;" ::: "memory");
    };

    float acc[2][4][4];
    #pragma unroll
    for (int i = 0; i < 2; i++)
        #pragma unroll
        for (int j = 0; j < 4; j++)
            #pragma unroll
            for (int r = 0; r < 4; r++) acc[i][j][r] = 0.0f;

    #pragma unroll
    for (int s = 0; s < STAGES2 - 1; s++) load_stage(s, s);

    const uint32_t lrow = lane & 15;
    const uint32_t lhalf = lane >> 4;
    const uint32_t lswz = lane & 7;
    const uint32_t a_rowbyte = (wm * 32 + lrow) * 128;
    const uint32_t b_rowbyte = (wn * 32 + lrow) * 128;
    uint32_t coff[4];
    #pragma unroll
    for (int k16 = 0; k16 < 4; k16++)
        coff[k16] = (((uint32_t)k16 * 2 + lhalf) ^ lswz) << 4;

    // double-buffered fragments (acc 32 + frags 2x16 -> ~106 regs, under cap)
    uint32_t a[2][2][4], b[2][2][4];

    for (int it = 0; it < nk; it++) {
        if (it + 1 < nk) asm volatile("cp.async.wait_group 1;" ::: "memory");
        else             asm volatile("cp.async.wait_group 0;" ::: "memory");
        __syncthreads();
        if (it + STAGES2 - 1 < nk) load_stage(it + STAGES2 - 1, (it + STAGES2 - 1) % STAGES2);

        const uint32_t abase = sb + (it % STAGES2) * STG2_BYTES;
        const uint32_t bbase = abase + BM2 * 128;

        // prime k16=0
        #pragma unroll
        for (int mi = 0; mi < 2; mi++)
            ldsm4(a[0][mi][0], a[0][mi][1], a[0][mi][2], a[0][mi][3],
                  abase + a_rowbyte + mi * 2048 + coff[0]);
        #pragma unroll
        for (int ni = 0; ni < 2; ni++)
            ldsm4(b[0][ni][0], b[0][ni][1], b[0][ni][2], b[0][ni][3],
                  bbase + b_rowbyte + ni * 2048 + coff[0]);

        #pragma unroll
        for (int k16 = 0; k16 < 4; k16++) {
            const int cur = k16 & 1;
            if (k16 < 3) {                     // prefetch next k16's fragments
                const int nxt = cur ^ 1;
                #pragma unroll
                for (int mi = 0; mi < 2; mi++)
                    ldsm4(a[nxt][mi][0], a[nxt][mi][1], a[nxt][mi][2], a[nxt][mi][3],
                          abase + a_rowbyte + mi * 2048 + coff[k16 + 1]);
                #pragma unroll
                for (int ni = 0; ni < 2; ni++)
                    ldsm4(b[nxt][ni][0], b[nxt][ni][1], b[nxt][ni][2], b[nxt][ni][3],
                          bbase + b_rowbyte + ni * 2048 + coff[k16 + 1]);
            }
            #pragma unroll
            for (int mi = 0; mi < 2; mi++)
                #pragma unroll
                for (int nj = 0; nj < 4; nj++)
                    mma16816(acc[mi][nj],
                             a[cur][mi][0], a[cur][mi][1], a[cur][mi][2], a[cur][mi][3],
                             b[cur][nj >> 1][nj & 1], b[cur][nj >> 1][(nj & 1) + 2]);
        }
    }

    #pragma unroll
    for (int mi = 0; mi < 2; mi++) {
        const size_t r0 = m0 + wm * 32 + mi * 16 + (lane >> 2);
        const size_t r1 = r0 + 8;
        const float i0 = rinv[r0];
        const float i1 = rinv[r1];
        #pragma unroll
        for (int nj = 0; nj < 4; nj++) {
            const size_t col = n0 + wn * 32 + nj * 8 + (lane & 3) * 2;
            float* c = acc[mi][nj];
            *reinterpret_cast<float2*>(&C[r0 * (size_t)N + col]) =
                make_float2(c[0] * i0, c[1] * i0);
            *reinterpret_cast<float2*>(&C[r1 * (size_t)N + col]) =
                make_float2(c[2] * i1, c[3] * i1);
        }
    }
}

// ---------------- launch ------------------------------------------------------
extern "C" void kernel_launch(void* const* d_in, const int* in_sizes, int n_in,
                              void* d_out, int out_size) {
    const float* q = (const float*)d_in[0];   // (4096, 4096)  Q[n][i]
    const float* k = (const float*)d_in[1];   // (4096, 8192)  K[n][j]
    const float* v = (const float*)d_in[2];   // (4096, 8192)  V[v][j]
    float* out = (float*)d_out;               // (4096, 4096)  out[i][v]

    __half *pQt, *pKt, *pVc, *pP;
    float *pPsum, *pRinv;
    cudaGetSymbolAddress((void**)&pQt,   g_Qt);
    cudaGetSymbolAddress((void**)&pKt,   g_Kt);
    cudaGetSymbolAddress((void**)&pVc,   g_Vc);
    cudaGetSymbolAddress((void**)&pP,    g_P);
    cudaGetSymbolAddress((void**)&pPsum, g_psum);
    cudaGetSymbolAddress((void**)&pRinv, g_rinv);

    cudaFuncSetAttribute(gemm1_mma, cudaFuncAttributeMaxDynamicSharedMemorySize, SMEM1_SZ);
    cudaFuncSetAttribute(gemm2_mma, cudaFuncAttributeMaxDynamicSharedMemorySize, SMEM2_SZ);

    // Qt[i][n] = Q[n][i]
    transpose_f2h_v<<<dim3(QDIM / 64, NDIM / 64), 256>>>(q, pQt, NDIM, QDIM);
    // Kt[j][n] = K[n][j]
    transpose_f2h_v<<<dim3(MDIM / 64, NDIM / 64), 256>>>(k, pKt, NDIM, MDIM);
    // Vc straight convert
    {
        size_t n = (size_t)VDIM * MDIM;
        convert_f2h<<<(unsigned)(n / 4 / 256), 256>>>(v, pVc, n);
    }

    // GEMM1 + fused exp + partial row sums
    gemm1_mma<<<dim3(MDIM / BN1, QDIM / BM1), 512, SMEM1_SZ>>>(
        pQt, pKt, pP, pPsum, QDIM, MDIM, NDIM);

    // reduce partials -> reciprocals
    rowsum_recip2<<<QDIM / 8, 256>>>(pPsum, pRinv);

    // GEMM2 + fused normalize
    gemm2_mma<<<dim3(VDIM / BN2, QDIM / BM2), 512, SMEM2_SZ>>>(
        pP, pVc, out, QDIM, VDIM, MDIM, pRinv);
}

// round 17
// speedup vs baseline: 1.0219x; 1.0219x over previous
#include <cuda_runtime.h>
#include <cuda_fp16.h>
#include <cstdint>

#define QDIM 4096   // q_dim (output rows i)
#define NDIM 4096   // contraction of GEMM1 (n)
#define MDIM 8192   // softmax dim / contraction of GEMM2 (j)
#define VDIM 4096   // v_dim (output cols v)
#define GX1  (MDIM / 256)   // GEMM1 grid.x = 32 partials per row

// ---------------- scratch (static device globals) ---------------------------
__device__ __half g_Qt[(size_t)QDIM * NDIM];   // Qt[i][n] = Q[n][i]
__device__ __half g_Kt[(size_t)MDIM * NDIM];   // Kt[j][n] = K[n][j]
__device__ __half g_Vc[(size_t)VDIM * MDIM];   // Vc[v][j] = V[v][j]
__device__ __half g_P [(size_t)QDIM * MDIM];   // exp(s) UNNORMALIZED fp16
__device__ float  g_psum[(size_t)QDIM * GX1];  // per-CTA partial row sums
__device__ float  g_rinv[QDIM];                // 1 / row sums

// ---------------- helpers ----------------------------------------------------
__device__ __forceinline__ uint32_t smem_u32(const void* p) {
    uint32_t a;
    asm("{ .reg .u64 t; cvta.to.shared.u64 t, %1; cvt.u32.u64 %0, t; }" : "=r"(a) : "l"(p));
    return a;
}
__device__ __forceinline__ void cp16(uint32_t dst, const void* src) {
    asm volatile("cp.async.cg.shared.global [%0], [%1], 16;" :: "r"(dst), "l"(src));
}
__device__ __forceinline__ void ldsm4(uint32_t& r0, uint32_t& r1, uint32_t& r2, uint32_t& r3,
                                      uint32_t addr) {
    asm volatile("ldmatrix.sync.aligned.m8n8.x4.shared.b16 {%0,%1,%2,%3}, [%4];"
                 : "=r"(r0), "=r"(r1), "=r"(r2), "=r"(r3) : "r"(addr));
}
__device__ __forceinline__ void mma16816(float* d, uint32_t a0, uint32_t a1, uint32_t a2,
                                         uint32_t a3, uint32_t b0, uint32_t b1) {
    asm volatile(
        "mma.sync.aligned.m16n8k16.row.col.f32.f16.f16.f32 "
        "{%0,%1,%2,%3}, {%4,%5,%6,%7}, {%8,%9}, {%0,%1,%2,%3};"
        : "+f"(d[0]), "+f"(d[1]), "+f"(d[2]), "+f"(d[3])
        : "r"(a0), "r"(a1), "r"(a2), "r"(a3), "r"(b0), "r"(b1));
}

// ---------------- preprocessing ----------------------------------------------
// Vectorized 64x64 transpose: out[c][r] = (half) in[r][c].
__global__ __launch_bounds__(256)
void transpose_f2h_v(const float* __restrict__ in, __half* __restrict__ out,
                     int rows, int cols) {
    __shared__ float tile[64][65];
    const int c0 = blockIdx.x * 64, r0 = blockIdx.y * 64;
    const int tid = threadIdx.x;
    const int lr = tid >> 4, lc = tid & 15;
    #pragma unroll
    for (int i = 0; i < 4; i++) {
        int r = lr + i * 16;
        float4 v = *reinterpret_cast<const float4*>(&in[(size_t)(r0 + r) * cols + c0 + lc * 4]);
        tile[r][lc * 4 + 0] = v.x; tile[r][lc * 4 + 1] = v.y;
        tile[r][lc * 4 + 2] = v.z; tile[r][lc * 4 + 3] = v.w;
    }
    __syncthreads();
    const int oc = tid >> 3, och = tid & 7;
    #pragma unroll
    for (int i = 0; i < 2; i++) {
        int c = oc + i * 32;
        __half h[8];
        #pragma unroll
        for (int j = 0; j < 8; j++) h[j] = __float2half(tile[och * 8 + j][c]);
        *reinterpret_cast<uint4*>(&out[(size_t)(c0 + c) * rows + r0 + och * 8]) =
            *reinterpret_cast<uint4*>(h);
    }
}

__global__ void convert_f2h(const float* __restrict__ in, __half* __restrict__ out, size_t n) {
    size_t i = ((size_t)blockIdx.x * blockDim.x + threadIdx.x) * 4;
    if (i + 3 < n) {
        float4 v = *reinterpret_cast<const float4*>(in + i);
        *reinterpret_cast<__half2*>(out + i)     = __floats2half2_rn(v.x, v.y);
        *reinterpret_cast<__half2*>(out + i + 2) = __floats2half2_rn(v.z, v.w);
    }
}

// =============================================================================
// GEMM1 (R13 measured 702-706us, untouched): 512 thr, 128x256, warp 32x64,
// 4 stages, unrolled by 4. C = exp(scale*acc) fp16 + fused psum.
// =============================================================================
#define BM1 128
#define BN1 256
#define BKC 64
#define STAGES1 4
#define STG1_BYTES ((BM1 + BN1) * 128)        // 48 KB
#define SMEM1_SZ (STAGES1 * STG1_BYTES)       // 192 KB

__global__ __launch_bounds__(512, 1)
void gemm1_mma(const __half* __restrict__ A, const __half* __restrict__ B,
               __half* __restrict__ C, float* __restrict__ psum,
               int M, int N, int K) {
    extern __shared__ char smem[];
    const uint32_t sb = smem_u32(smem);
    const int tid = threadIdx.x;
    const int wid = tid >> 5;
    const int lane = tid & 31;
    const int wm = wid & 3;
    const int wn = wid >> 2;
    const size_t m0 = (size_t)blockIdx.y * BM1;
    const size_t n0 = (size_t)blockIdx.x * BN1;
    const int nk = K / BKC;

    const int ldrow = tid >> 3;
    const int ldc16 = tid & 7;
    const uint32_t swz_st = ((uint32_t)ldc16 ^ ((uint32_t)ldrow & 7)) << 4;

    auto load_stage = [&](int c, int buf) {
        const uint32_t abase = sb + buf * STG1_BYTES;
        const uint32_t bbase = abase + BM1 * 128;
        const size_t k0 = (size_t)c * BKC;
        #pragma unroll
        for (int i = 0; i < 2; i++) {
            int row = ldrow + i * 64;
            cp16(abase + row * 128 + swz_st, A + (m0 + row) * (size_t)K + k0 + ldc16 * 8);
        }
        #pragma unroll
        for (int i = 0; i < 4; i++) {
            int row = ldrow + i * 64;
            cp16(bbase + row * 128 + swz_st, B + (n0 + row) * (size_t)K + k0 + ldc16 * 8);
        }
        asm volatile("cp.async.commit_group;" ::: "memory");
    };

    float acc[2][8][4];
    #pragma unroll
    for (int i = 0; i < 2; i++)
        #pragma unroll
        for (int j = 0; j < 8; j++)
            #pragma unroll
            for (int r = 0; r < 4; r++) acc[i][j][r] = 0.0f;

    #pragma unroll
    for (int s = 0; s < STAGES1 - 1; s++) load_stage(s, s);

    const uint32_t lrow = lane & 15;
    const uint32_t lhalf = lane >> 4;
    const uint32_t lswz = lane & 7;
    const uint32_t a_rowbyte = (wm * 32 + lrow) * 128;
    const uint32_t b_rowbyte = (wn * 64 + lrow) * 128;
    uint32_t coff[4];
    #pragma unroll
    for (int k16 = 0; k16 < 4; k16++)
        coff[k16] = (((uint32_t)k16 * 2 + lhalf) ^ lswz) << 4;

    for (int it0 = 0; it0 < nk; it0 += STAGES1) {
        #pragma unroll
        for (int u = 0; u < STAGES1; u++) {
            const int it = it0 + u;
            const int rem = nk - 1 - it;
            if (rem >= 2)      asm volatile("cp.async.wait_group 2;" ::: "memory");
            else if (rem == 1) asm volatile("cp.async.wait_group 1;" ::: "memory");
            else               asm volatile("cp.async.wait_group 0;" ::: "memory");
            __syncthreads();
            if (it + STAGES1 - 1 < nk)
                load_stage(it + STAGES1 - 1, (u + STAGES1 - 1) % STAGES1);

            const uint32_t abase = sb + u * STG1_BYTES;
            const uint32_t bbase = abase + BM1 * 128;

            #pragma unroll
            for (int k16 = 0; k16 < 4; k16++) {
                uint32_t a[2][4], b[4][4];
                #pragma unroll
                for (int mi = 0; mi < 2; mi++)
                    ldsm4(a[mi][0], a[mi][1], a[mi][2], a[mi][3],
                          abase + a_rowbyte + mi * 2048 + coff[k16]);
                #pragma unroll
                for (int ni = 0; ni < 4; ni++)
                    ldsm4(b[ni][0], b[ni][1], b[ni][2], b[ni][3],
                          bbase + b_rowbyte + ni * 2048 + coff[k16]);
                #pragma unroll
                for (int mi = 0; mi < 2; mi++)
                    #pragma unroll
                    for (int nj = 0; nj < 8; nj++)
                        mma16816(acc[mi][nj], a[mi][0], a[mi][1], a[mi][2], a[mi][3],
                                 b[nj >> 1][nj & 1], b[nj >> 1][(nj & 1) + 2]);
            }
        }
    }

    const float scale = 0.015625f;     // 1/sqrt(4096)
    float s0[2], s1[2];
    #pragma unroll
    for (int mi = 0; mi < 2; mi++) { s0[mi] = 0.0f; s1[mi] = 0.0f; }
    #pragma unroll
    for (int mi = 0; mi < 2; mi++) {
        const size_t r0 = m0 + wm * 32 + mi * 16 + (lane >> 2);
        const size_t r1 = r0 + 8;
        #pragma unroll
        for (int nj = 0; nj < 8; nj++) {
            const size_t col = n0 + wn * 64 + nj * 8 + (lane & 3) * 2;
            float* c = acc[mi][nj];
            float e0 = __expf(c[0] * scale), e1 = __expf(c[1] * scale);
            float e2 = __expf(c[2] * scale), e3 = __expf(c[3] * scale);
            *reinterpret_cast<__half2*>(&C[r0 * (size_t)N + col]) = __floats2half2_rn(e0, e1);
            *reinterpret_cast<__half2*>(&C[r1 * (size_t)N + col]) = __floats2half2_rn(e2, e3);
            s0[mi] += e0 + e1;
            s1[mi] += e2 + e3;
        }
    }
    float* red = reinterpret_cast<float*>(smem);
    __syncthreads();
    #pragma unroll
    for (int mi = 0; mi < 2; mi++) {
        float a = s0[mi], b = s1[mi];
        a += __shfl_xor_sync(0xFFFFFFFFu, a, 1);
        a += __shfl_xor_sync(0xFFFFFFFFu, a, 2);
        b += __shfl_xor_sync(0xFFFFFFFFu, b, 1);
        b += __shfl_xor_sync(0xFFFFFFFFu, b, 2);
        if ((lane & 3) == 0) {
            int rl = wm * 32 + mi * 16 + (lane >> 2);
            red[rl * 4 + wn] = a;
            red[(rl + 8) * 4 + wn] = b;
        }
    }
    __syncthreads();
    if (tid < BM1) {
        float s = red[tid * 4] + red[tid * 4 + 1] + red[tid * 4 + 2] + red[tid * 4 + 3];
        psum[(m0 + tid) * GX1 + blockIdx.x] = s;
    }
}

// ---------------- reduce psum partials -> rinv -------------------------------
__global__ __launch_bounds__(256)
void rowsum_recip2(const float* __restrict__ psum, float* __restrict__ rinv) {
    const int row = blockIdx.x * 8 + (threadIdx.x >> 5);
    const int lane = threadIdx.x & 31;
    float v = psum[(size_t)row * GX1 + lane];
    #pragma unroll
    for (int o = 16; o > 0; o >>= 1) v += __shfl_xor_sync(0xFFFFFFFFu, v, o);
    if (lane == 0) rinv[row] = 1.0f / v;
}

// =============================================================================
// GEMM2: 512 thr, 128x128, warp 32x32, 3 stages, 2 CTAs/SM.
// Compile-time nk=128: guard-free unroll-by-3 over iters [0,126) + 2 peeled
// tail iterations (buffers 0 and 1, literal). C = acc * rinv[row] fp32
// =============================================================================
#define BM2 128
#define BN2 128
#define STAGES2 3
#define NK2 (MDIM / BKC)                      // 128 (compile-time)
#define STG2_BYTES ((BM2 + BN2) * 128)        // 32 KB
#define SMEM2_SZ (STAGES2 * STG2_BYTES)       // 96 KB

__global__ __launch_bounds__(512, 2)
void gemm2_mma(const __half* __restrict__ A, const __half* __restrict__ B,
               float* __restrict__ C, int M, int N,
               const float* __restrict__ rinv) {
    extern __shared__ char smem[];
    const uint32_t sb = smem_u32(smem);
    const int tid = threadIdx.x;
    const int wid = tid >> 5;
    const int lane = tid & 31;
    const int wm = wid & 3;            // 4 warps over M -> 32 rows
    const int wn = wid >> 2;           // 4 warps over N -> 32 cols
    const size_t m0 = (size_t)blockIdx.y * BM2;
    const size_t n0 = (size_t)blockIdx.x * BN2;
    constexpr int K = MDIM;

    const int ldrow = tid >> 3;
    const int ldc16 = tid & 7;
    const uint32_t swz_st = ((uint32_t)ldc16 ^ ((uint32_t)ldrow & 7)) << 4;

    auto load_stage = [&](int c, int buf) {
        const uint32_t abase = sb + buf * STG2_BYTES;
        const uint32_t bbase = abase + BM2 * 128;
        const size_t k0 = (size_t)c * BKC;
        #pragma unroll
        for (int i = 0; i < 2; i++) {
            int row = ldrow + i * 64;
            cp16(abase + row * 128 + swz_st, A + (m0 + row) * (size_t)K + k0 + ldc16 * 8);
        }
        #pragma unroll
        for (int i = 0; i < 2; i++) {
            int row = ldrow + i * 64;
            cp16(bbase + row * 128 + swz_st, B + (n0 + row) * (size_t)K + k0 + ldc16 * 8);
        }
        asm volatile("cp.async.commit_group;" ::: "memory");
    };

    float acc[2][4][4];
    #pragma unroll
    for (int i = 0; i < 2; i++)
        #pragma unroll
        for (int j = 0; j < 4; j++)
            #pragma unroll
            for (int r = 0; r < 4; r++) acc[i][j][r] = 0.0f;

    #pragma unroll
    for (int s = 0; s < STAGES2 - 1; s++) load_stage(s, s);

    const uint32_t lrow = lane & 15;
    const uint32_t lhalf = lane >> 4;
    const uint32_t lswz = lane & 7;
    const uint32_t a_rowbyte = (wm * 32 + lrow) * 128;
    const uint32_t b_rowbyte = (wn * 32 + lrow) * 128;
    uint32_t coff[4];
    #pragma unroll
    for (int k16 = 0; k16 < 4; k16++)
        coff[k16] = (((uint32_t)k16 * 2 + lhalf) ^ lswz) << 4;

    // compute body for one 64-k chunk out of buffer `u` (compile-time)
    auto compute_buf = [&](uint32_t abase) {
        const uint32_t bbase = abase + BM2 * 128;
        #pragma unroll
        for (int k16 = 0; k16 < 4; k16++) {
            uint32_t a[2][4], b[2][4];
            #pragma unroll
            for (int mi = 0; mi < 2; mi++)
                ldsm4(a[mi][0], a[mi][1], a[mi][2], a[mi][3],
                      abase + a_rowbyte + mi * 2048 + coff[k16]);
            #pragma unroll
            for (int ni = 0; ni < 2; ni++)
                ldsm4(b[ni][0], b[ni][1], b[ni][2], b[ni][3],
                      bbase + b_rowbyte + ni * 2048 + coff[k16]);
            #pragma unroll
            for (int mi = 0; mi < 2; mi++)
                #pragma unroll
                for (int nj = 0; nj < 4; nj++)
                    mma16816(acc[mi][nj], a[mi][0], a[mi][1], a[mi][2], a[mi][3],
                             b[nj >> 1][nj & 1], b[nj >> 1][(nj & 1) + 2]);
        }
    };

    // main loop: iters [0, NK2-2), 42 clean rounds of 3, NO guards
    for (int it0 = 0; it0 < NK2 - 2; it0 += STAGES2) {
        #pragma unroll
        for (int u = 0; u < STAGES2; u++) {
            const int it = it0 + u;
            asm volatile("cp.async.wait_group 1;" ::: "memory");
            __syncthreads();
            load_stage(it + STAGES2 - 1, (u + STAGES2 - 1) % STAGES2);
            compute_buf(sb + u * STG2_BYTES);          // compile-time buffer
        }
    }
    // peeled tail: it = 126 -> buffer 0 ; it = 127 -> buffer 1  (NK2 = 128)
    asm volatile("cp.async.wait_group 1;" ::: "memory");
    __syncthreads();
    compute_buf(sb + 0 * STG2_BYTES);
    asm volatile("cp.async.wait_group 0;" ::: "memory");
    __syncthreads();
    compute_buf(sb + 1 * STG2_BYTES);

    #pragma unroll
    for (int mi = 0; mi < 2; mi++) {
        const size_t r0 = m0 + wm * 32 + mi * 16 + (lane >> 2);
        const size_t r1 = r0 + 8;
        const float i0 = rinv[r0];
        const float i1 = rinv[r1];
        #pragma unroll
        for (int nj = 0; nj < 4; nj++) {
            const size_t col = n0 + wn * 32 + nj * 8 + (lane & 3) * 2;
            float* c = acc[mi][nj];
            *reinterpret_cast<float2*>(&C[r0 * (size_t)N + col]) =
                make_float2(c[0] * i0, c[1] * i0);
            *reinterpret_cast<float2*>(&C[r1 * (size_t)N + col]) =
                make_float2(c[2] * i1, c[3] * i1);
        }
    }
}

// ---------------- launch ------------------------------------------------------
extern "C" void kernel_launch(void* const* d_in, const int* in_sizes, int n_in,
                              void* d_out, int out_size) {
    const float* q = (const float*)d_in[0];   // (4096, 4096)  Q[n][i]
    const float* k = (const float*)d_in[1];   // (4096, 8192)  K[n][j]
    const float* v = (const float*)d_in[2];   // (4096, 8192)  V[v][j]
    float* out = (float*)d_out;               // (4096, 4096)  out[i][v]

    __half *pQt, *pKt, *pVc, *pP;
    float *pPsum, *pRinv;
    cudaGetSymbolAddress((void**)&pQt,   g_Qt);
    cudaGetSymbolAddress((void**)&pKt,   g_Kt);
    cudaGetSymbolAddress((void**)&pVc,   g_Vc);
    cudaGetSymbolAddress((void**)&pP,    g_P);
    cudaGetSymbolAddress((void**)&pPsum, g_psum);
    cudaGetSymbolAddress((void**)&pRinv, g_rinv);

    cudaFuncSetAttribute(gemm1_mma, cudaFuncAttributeMaxDynamicSharedMemorySize, SMEM1_SZ);
    cudaFuncSetAttribute(gemm2_mma, cudaFuncAttributeMaxDynamicSharedMemorySize, SMEM2_SZ);

    // Qt[i][n] = Q[n][i]
    transpose_f2h_v<<<dim3(QDIM / 64, NDIM / 64), 256>>>(q, pQt, NDIM, QDIM);
    // Kt[j][n] = K[n][j]
    transpose_f2h_v<<<dim3(MDIM / 64, NDIM / 64), 256>>>(k, pKt, NDIM, MDIM);
    // Vc straight convert
    {
        size_t n = (size_t)VDIM * MDIM;
        convert_f2h<<<(unsigned)(n / 4 / 256), 256>>>(v, pVc, n);
    }

    // GEMM1 + fused exp + partial row sums
    gemm1_mma<<<dim3(MDIM / BN1, QDIM / BM1), 512, SMEM1_SZ>>>(
        pQt, pKt, pP, pPsum, QDIM, MDIM, NDIM);

    // reduce partials -> reciprocals
    rowsum_recip2<<<QDIM / 8, 256>>>(pPsum, pRinv);

    // GEMM2 + fused normalize
    gemm2_mma<<<dim3(VDIM / BN2, QDIM / BM2), 512, SMEM2_SZ>>>(
        pP, pVc, out, QDIM, VDIM, pRinv);
}